// round 2
// baseline (speedup 1.0000x reference)
#include <cuda_runtime.h>

#define SDIM 128
#define S3 (SDIM*SDIM*SDIM)
#define NBATCH 2
#define NPTS 250000
#define MTOT (NBATCH*NPTS)
#define CCH 32

// ---- static device scratch (allocation-free rule: __device__ globals) ----
__device__ int   g_grid[NBATCH*S3];      // 16.8 MB dense voxel grid
__device__ int   g_cnt [MTOT];           // valid-neighbor count per point
__device__ int   g_nbr [MTOT*27];        // packed (k<<24)|idx, compacted to front
__device__ float g_buf1[MTOT*CCH];       // 64 MB intermediate
__device__ float g_buf2[MTOT*CCH];       // 64 MB intermediate

// ---------------------------------------------------------------
__global__ void clear_grid_kernel() {
    int i = blockIdx.x*blockDim.x + threadIdx.x;   // 4096*256 threads == S3*NBATCH/4
    ((int4*)g_grid)[i] = make_int4(-1,-1,-1,-1);
}

__global__ void scatter_kernel(const int* __restrict__ coords) {
    int p = blockIdx.x*blockDim.x + threadIdx.x;
    if (p >= MTOT) return;
    int cx = coords[3*p], cy = coords[3*p+1], cz = coords[3*p+2];
    int b  = p / NPTS;
    g_grid[b*S3 + (cx*SDIM + cy)*SDIM + cz] = p;
}

__global__ void build_nbr_kernel(const int* __restrict__ coords) {
    int p = blockIdx.x*blockDim.x + threadIdx.x;
    if (p >= MTOT) return;
    int cx = coords[3*p], cy = coords[3*p+1], cz = coords[3*p+2];
    const int* gb = g_grid + (p / NPTS) * S3;
    int n = 0;
    int* row = g_nbr + p*27;
    #pragma unroll
    for (int dx = 0; dx < 3; dx++) {
        int nx = cx + dx - 1;
        if ((unsigned)nx >= SDIM) continue;
        #pragma unroll
        for (int dy = 0; dy < 3; dy++) {
            int ny = cy + dy - 1;
            if ((unsigned)ny >= SDIM) continue;
            int base = (nx*SDIM + ny)*SDIM;
            #pragma unroll
            for (int dz = 0; dz < 3; dz++) {
                int nz = cz + dz - 1;
                if ((unsigned)nz >= SDIM) continue;
                int idx = gb[base + nz];
                if (idx >= 0) row[n++] = (((dx*3+dy)*3+dz) << 24) | idx;
            }
        }
    }
    g_cnt[p] = n;
}

// ---------------------------------------------------------------
#define CONV_THREADS 256
#define CONV_WARPS   8
#define SMEM_FLOATS  (27*CCH*CCH + CONV_WARPS*CCH)   // W (108 KB) + per-warp f staging

// mode: 0 = external ptr, 1 = g_buf1, 2 = g_buf2
template<bool RELU>
__global__ void __launch_bounds__(CONV_THREADS, 2)
subm_conv_kernel(const float* __restrict__ fext_in, float* __restrict__ fext_out,
                 const float* __restrict__ Wg, int in_mode, int out_mode)
{
    extern __shared__ float smem[];
    float* sW = smem;                          // 27*32*32
    float* sF = smem + 27*CCH*CCH;             // 8 warps * 32

    const float* fin  = (in_mode  == 0) ? fext_in  : (in_mode  == 1 ? g_buf1 : g_buf2);
    float*       fout = (out_mode == 0) ? fext_out : (out_mode == 1 ? g_buf1 : g_buf2);

    // Stage full weight tensor into shared memory (once per CTA)
    for (int i = threadIdx.x; i < 27*CCH*CCH; i += CONV_THREADS)
        sW[i] = Wg[i];
    __syncthreads();

    const int warp = threadIdx.x >> 5;
    const int lane = threadIdx.x & 31;
    float* myF = sF + warp*CCH;

    for (int p = blockIdx.x*CONV_WARPS + warp; p < MTOT; p += gridDim.x*CONV_WARPS) {
        const int cn = g_cnt[p];
        int ment = 0;
        if (lane < cn) ment = g_nbr[p*27 + lane];   // each lane holds one rulebook entry

        float a0 = 0.f, a1 = 0.f, a2 = 0.f, a3 = 0.f;

        int   ent = __shfl_sync(0xFFFFFFFFu, ment, 0);
        float v   = fin[(ent & 0xFFFFFF)*CCH + lane];   // prefetch first gather

        for (int e = 0; e < cn; e++) {
            const int k = ent >> 24;
            myF[lane] = v;
            __syncwarp();

            // prefetch next neighbor's feature row (hides L2 latency under FMAs)
            int nsel = e + 1; if (nsel > 26) nsel = 26;
            int   nent = __shfl_sync(0xFFFFFFFFu, ment, nsel);
            float nv   = fin[(nent & 0xFFFFFF)*CCH + lane];

            const float* Wk = sW + k*(CCH*CCH);
            #pragma unroll
            for (int j = 0; j < CCH; j += 4) {
                float4 f4 = *(const float4*)(myF + j);          // LDS.128 broadcast
                a0 = fmaf(f4.x, Wk[(j+0)*CCH + lane], a0);      // conflict-free LDS
                a1 = fmaf(f4.y, Wk[(j+1)*CCH + lane], a1);
                a2 = fmaf(f4.z, Wk[(j+2)*CCH + lane], a2);
                a3 = fmaf(f4.w, Wk[(j+3)*CCH + lane], a3);
            }
            __syncwarp();
            ent = nent;
            v   = nv;
        }

        float r = (a0 + a1) + (a2 + a3);
        if (RELU) r = fmaxf(r, 0.f);
        fout[p*CCH + lane] = r;
    }
}

// ---------------------------------------------------------------
extern "C" void kernel_launch(void* const* d_in, const int* in_sizes, int n_in,
                              void* d_out, int out_size)
{
    const float* features = (const float*)d_in[0];
    const int*   coords   = (const int*)  d_in[1];
    // weights are the last three inputs regardless of metadata middle entries
    const float* W1 = (const float*)d_in[n_in-3];
    const float* W2 = (const float*)d_in[n_in-2];
    const float* W3 = (const float*)d_in[n_in-1];
    float* out = (float*)d_out;

    const size_t smem_bytes = SMEM_FLOATS * sizeof(float);   // 111,616 B
    // Non-stream-ordered, idempotent; legal during graph capture.
    cudaFuncSetAttribute(subm_conv_kernel<true>,
                         cudaFuncAttributeMaxDynamicSharedMemorySize, (int)smem_bytes);
    cudaFuncSetAttribute(subm_conv_kernel<false>,
                         cudaFuncAttributeMaxDynamicSharedMemorySize, (int)smem_bytes);

    // 1) rebuild grid + rulebook every call (deterministic, graph-capturable)
    clear_grid_kernel<<<(NBATCH*S3/4)/256, 256>>>();
    scatter_kernel  <<<(MTOT+255)/256, 256>>>(coords);
    build_nbr_kernel<<<(MTOT+255)/256, 256>>>(coords);

    // 2) three conv layers, persistent grid (2 CTAs/SM x 148 SMs)
    const int nblk = 148*2;
    subm_conv_kernel<true ><<<nblk, CONV_THREADS, smem_bytes>>>(features, nullptr, W1, 0, 1);
    subm_conv_kernel<true ><<<nblk, CONV_THREADS, smem_bytes>>>(nullptr,  nullptr, W2, 1, 2);
    subm_conv_kernel<false><<<nblk, CONV_THREADS, smem_bytes>>>(nullptr,  out,     W3, 2, 0);
}

// round 3
// speedup vs baseline: 1.1844x; 1.1844x over previous
#include <cuda_runtime.h>

#define SDIM 128
#define S3 (SDIM*SDIM*SDIM)
#define NBATCH 2
#define NPTS 250000
#define MTOT (NBATCH*NPTS)
#define CCH 32
#define NK 27

// ---- static device scratch (allocation-free rule) ----
__device__ int   g_grid[NBATCH*S3];      // 16.8 MB dense voxel grid
__device__ int   g_mask[MTOT];           // 27-bit presence mask per output point
__device__ int   g_pin [NK*MTOT];        // in_idx for pair (k, out p); valid iff mask bit k
__device__ float g_tmp [NK*MTOT*CCH];    // 1.73 GB partial rows, indexed (k, p); only valid rows touched
__device__ float g_buf1[MTOT*CCH];       // 64 MB layer buffer
__device__ float g_buf2[MTOT*CCH];       // 64 MB layer buffer

// ---------------------------------------------------------------
__global__ void clear_grid_kernel() {
    int i = blockIdx.x*blockDim.x + threadIdx.x;   // 4096*256 == S3*NBATCH/4
    ((int4*)g_grid)[i] = make_int4(-1,-1,-1,-1);
}

__global__ void scatter_kernel(const int* __restrict__ coords) {
    int p = blockIdx.x*blockDim.x + threadIdx.x;
    if (p >= MTOT) return;
    int cx = coords[3*p], cy = coords[3*p+1], cz = coords[3*p+2];
    int b  = p / NPTS;
    g_grid[b*S3 + (cx*SDIM + cy)*SDIM + cz] = p;
}

__global__ void build_kernel(const int* __restrict__ coords) {
    int p = blockIdx.x*blockDim.x + threadIdx.x;
    if (p >= MTOT) return;
    int cx = coords[3*p], cy = coords[3*p+1], cz = coords[3*p+2];
    const int* gb = g_grid + (p / NPTS) * S3;
    int m = 0;
    #pragma unroll
    for (int dx = 0; dx < 3; dx++) {
        int nx = cx + dx - 1;
        if ((unsigned)nx >= SDIM) continue;
        #pragma unroll
        for (int dy = 0; dy < 3; dy++) {
            int ny = cy + dy - 1;
            if ((unsigned)ny >= SDIM) continue;
            int base = (nx*SDIM + ny)*SDIM;
            #pragma unroll
            for (int dz = 0; dz < 3; dz++) {
                int nz = cz + dz - 1;
                if ((unsigned)nz >= SDIM) continue;
                int idx = gb[base + nz];
                if (idx >= 0) {
                    int k = (dx*3 + dy)*3 + dz;
                    m |= (1 << k);
                    g_pin[k*MTOT + p] = idx;
                }
            }
        }
    }
    g_mask[p] = m;
}

// ---------------------------------------------------------------
// Phase 1: per-offset gather-GEMV. blockIdx.y = k. Warp owns 128 output
// points for this k; W[k] column lives in 32 registers per lane.
#define P1_THREADS 256
#define P1_WARPS   8
#define P1_CHUNK   128          // points per warp (4 sub-chunks of 32)

// in_mode: 0 = external, 1 = g_buf1, 2 = g_buf2
__global__ void __launch_bounds__(P1_THREADS)
conv_pairs_kernel(const float* __restrict__ fext_in, const float* __restrict__ Wg,
                  int in_mode)
{
    __shared__ float sF[P1_WARPS][CCH];
    const int warp = threadIdx.x >> 5;
    const int lane = threadIdx.x & 31;
    const int k    = blockIdx.y;
    const int base = (blockIdx.x*P1_WARPS + warp) * P1_CHUNK;
    if (base >= MTOT) return;

    const float* fin = (in_mode == 0) ? fext_in : (in_mode == 1 ? g_buf1 : g_buf2);

    // W[k] column -> registers (amortized over up to ~15-128 pairs)
    float w[CCH];
    #pragma unroll
    for (int j = 0; j < CCH; j++) w[j] = __ldg(&Wg[k*(CCH*CCH) + j*CCH + lane]);

    float* myF = sF[warp];
    const int kbase = k*MTOT;

    #pragma unroll 1
    for (int sub = 0; sub < P1_CHUNK/32; sub++) {
        const int p0 = base + sub*32;
        if (p0 >= MTOT) break;
        const int p = p0 + lane;
        int m = (p < MTOT) ? g_mask[p] : 0;
        unsigned act = __ballot_sync(0xFFFFFFFFu, (m >> k) & 1);
        if (!act) continue;
        int inidx = 0;
        if ((act >> lane) & 1) inidx = g_pin[kbase + p];   // coalesced, predicated

        // iterate set bits (warp-uniform), 1-deep prefetch of gathered row
        int q = __ffs(act) - 1;
        unsigned rem = act & (act - 1);
        int   idx = __shfl_sync(0xFFFFFFFFu, inidx, q);
        float v   = fin[idx*CCH + lane];

        while (true) {
            int   qn = -1;
            float vn = 0.f;
            if (rem) {                                      // warp-uniform branch
                qn = __ffs(rem) - 1; rem &= rem - 1;
                int idxn = __shfl_sync(0xFFFFFFFFu, inidx, qn);
                vn = fin[idxn*CCH + lane];                  // prefetch next row
            }

            myF[lane] = v;
            __syncwarp();
            float a0 = 0.f, a1 = 0.f, a2 = 0.f, a3 = 0.f;
            #pragma unroll
            for (int j = 0; j < CCH; j += 4) {
                float4 f4 = *(const float4*)(myF + j);      // broadcast LDS.128
                a0 = fmaf(f4.x, w[j+0], a0);                // W from registers
                a1 = fmaf(f4.y, w[j+1], a1);
                a2 = fmaf(f4.z, w[j+2], a2);
                a3 = fmaf(f4.w, w[j+3], a3);
            }
            __syncwarp();
            g_tmp[(kbase + p0 + q)*CCH + lane] = (a0 + a1) + (a2 + a3);

            if (qn < 0) break;
            q = qn; v = vn;
        }
    }
}

// ---------------------------------------------------------------
// Phase 2: per-point reduction over valid (k,p) partial rows, fused ReLU.
#define P2_THREADS 256

template<bool RELU>
__global__ void __launch_bounds__(P2_THREADS)
reduce_kernel(float* __restrict__ fext_out, int out_mode)
{
    const int wg   = blockIdx.x*(P2_THREADS/32) + (threadIdx.x >> 5);
    const int lane = threadIdx.x & 31;
    if (wg >= MTOT) return;
    const int p = wg;

    float* fout = (out_mode == 0) ? fext_out : (out_mode == 1 ? g_buf1 : g_buf2);

    int m = g_mask[p];
    float acc = 0.f;
    while (m) {                                  // 4-wide batched loads for MLP
        int k0 = __ffs(m) - 1; m &= m - 1;
        int k1 = -1, k2 = -1, k3 = -1;
        if (m) { k1 = __ffs(m) - 1; m &= m - 1; }
        if (m) { k2 = __ffs(m) - 1; m &= m - 1; }
        if (m) { k3 = __ffs(m) - 1; m &= m - 1; }
        float v0 = g_tmp[(k0*MTOT + p)*CCH + lane];
        float v1 = (k1 >= 0) ? g_tmp[(k1*MTOT + p)*CCH + lane] : 0.f;
        float v2 = (k2 >= 0) ? g_tmp[(k2*MTOT + p)*CCH + lane] : 0.f;
        float v3 = (k3 >= 0) ? g_tmp[(k3*MTOT + p)*CCH + lane] : 0.f;
        acc += (v0 + v1) + (v2 + v3);
    }
    if (RELU) acc = fmaxf(acc, 0.f);
    fout[p*CCH + lane] = acc;
}

// ---------------------------------------------------------------
extern "C" void kernel_launch(void* const* d_in, const int* in_sizes, int n_in,
                              void* d_out, int out_size)
{
    const float* features = (const float*)d_in[0];
    const int*   coords   = (const int*)  d_in[1];
    const float* W1 = (const float*)d_in[n_in-3];
    const float* W2 = (const float*)d_in[n_in-2];
    const float* W3 = (const float*)d_in[n_in-1];
    float* out = (float*)d_out;

    // 1) rebuild grid + rulebook (deterministic, no atomics)
    clear_grid_kernel<<<(NBATCH*S3/4)/256, 256>>>();
    scatter_kernel  <<<(MTOT+255)/256, 256>>>(coords);
    build_kernel    <<<(MTOT+255)/256, 256>>>(coords);

    // 2) three layers: k-major pair GEMV -> per-point reduce (+ReLU)
    dim3 g1((MTOT + P1_WARPS*P1_CHUNK - 1)/(P1_WARPS*P1_CHUNK), NK);
    const int g2 = (MTOT + (P2_THREADS/32) - 1) / (P2_THREADS/32);

    conv_pairs_kernel<<<g1, P1_THREADS>>>(features, W1, 0);
    reduce_kernel<true ><<<g2, P2_THREADS>>>(nullptr, 1);

    conv_pairs_kernel<<<g1, P1_THREADS>>>(nullptr, W2, 1);
    reduce_kernel<true ><<<g2, P2_THREADS>>>(nullptr, 2);

    conv_pairs_kernel<<<g1, P1_THREADS>>>(nullptr, W3, 2);
    reduce_kernel<false><<<g2, P2_THREADS>>>(out, 0);
}